// round 12
// baseline (speedup 1.0000x reference)
#include <cuda_runtime.h>
#include <cuda_bf16.h>
#include <cuda_fp16.h>
#include <cuda_fp8.h>
#include <math.h>

// Problem constants (from reference_code)
#define NN   50000
#define EE   1600000
#define ENT  (EE + NN)     // edges incl. self-loops = 1650000
#define DIN  512
#define HH   256
#define GG   16
#define SCAN_B ((NN + 255) / 256)   // 196 scan blocks

// ---------------- device scratch (static; no allocation allowed) ----------------
__device__ int   g_is64;                    // 1 if indices are int64, 0 if int32
__device__ int   g_cnt[NN];
__device__ float g_dinv[NN];
__device__ int   g_rowptr[NN + 1];
__device__ int   g_cursor[NN];
__device__ int   g_bsum[SCAN_B];            // per-block partial sums
__device__ int   g_boff[SCAN_B];            // per-block exclusive offsets
__device__ int   g_col[ENT];
__device__ float g_w[ENT];
__device__ float g_pooled[GG * HH];
__device__ int   g_gcount[GG];
// fp8 buffers (e4m3), 256B aligned for vector access
__device__ __align__(256) unsigned char g_X8[(size_t)NN * DIN];  // fp8(x), layer-1 A
__device__ __align__(256) unsigned char g_M8[(size_t)NN * HH];   // GEMM out (gather input)
__device__ __align__(256) unsigned char g_H8[(size_t)NN * HH];   // agg out (next A / pool)
__device__ __align__(256) unsigned char g_W8t[HH * DIN];         // fp8 W^T [n][k], k contig

// dtype-agnostic index load (flag-steered), clamped for crash-safety
__device__ __forceinline__ int load_idx(const void* p, long long i) {
    int v;
    if (g_is64) v = (int)((const long long*)p)[i];
    else        v = ((const int*)p)[i];
    return min(max(v, 0), NN - 1);
}
__device__ __forceinline__ int load_gidx(const void* p, long long i) {
    int v;
    if (g_is64) v = (int)((const long long*)p)[i];
    else        v = ((const int*)p)[i];
    return min(max(v, 0), GG - 1);
}

// ---------------- dtype probe ----------------
__global__ void k_probe(const unsigned int* __restrict__ w) {
    __shared__ int any;
    if (threadIdx.x == 0) any = 0;
    __syncthreads();
    for (int i = threadIdx.x; i < 2048; i += 256)
        if (w[2 * i + 1] != 0u) atomicOr(&any, 1);
    __syncthreads();
    if (threadIdx.x == 0) g_is64 = (any == 0) ? 1 : 0;
}

// ---------------- setup kernels ----------------
__global__ void k_init_cnt() {
    int i = blockIdx.x * blockDim.x + threadIdx.x;
    if (i < NN) g_cnt[i] = 1;
}

__global__ void k_count(const void* __restrict__ ei) {
    int i = blockIdx.x * blockDim.x + threadIdx.x;
    if (i < EE) atomicAdd(&g_cnt[load_idx(ei, (long long)EE + i)], 1);
}

__global__ void k_dinv() {
    int i = blockIdx.x * blockDim.x + threadIdx.x;
    if (i < NN) {
        g_dinv[i]   = rsqrtf((float)g_cnt[i]);
        g_cursor[i] = 0;
    }
}

// ---- 3-phase parallel exclusive scan of g_cnt -> g_rowptr ----
__global__ void k_scan1() {
    __shared__ int sh[256];
    int t = threadIdx.x;
    int i = blockIdx.x * 256 + t;
    sh[t] = (i < NN) ? g_cnt[i] : 0;
    __syncthreads();
    #pragma unroll
    for (int off = 128; off > 0; off >>= 1) {
        if (t < off) sh[t] += sh[t + off];
        __syncthreads();
    }
    if (t == 0) g_bsum[blockIdx.x] = sh[0];
}

__global__ void k_scan2() {
    __shared__ int sh[256];
    int t = threadIdx.x;
    int v = (t < SCAN_B) ? g_bsum[t] : 0;
    sh[t] = v;
    __syncthreads();
    #pragma unroll
    for (int off = 1; off < 256; off <<= 1) {
        int tv = (t >= off) ? sh[t - off] : 0;
        __syncthreads();
        sh[t] += tv;
        __syncthreads();
    }
    if (t < SCAN_B) g_boff[t] = sh[t] - v;   // exclusive
    if (t == 255) g_rowptr[NN] = sh[255];    // == ENT
}

__global__ void k_scan3() {
    __shared__ int sh[256];
    int t = threadIdx.x;
    int i = blockIdx.x * 256 + t;
    int v = (i < NN) ? g_cnt[i] : 0;
    sh[t] = v;
    __syncthreads();
    #pragma unroll
    for (int off = 1; off < 256; off <<= 1) {
        int tv = (t >= off) ? sh[t - off] : 0;
        __syncthreads();
        sh[t] += tv;
        __syncthreads();
    }
    if (i < NN) g_rowptr[i] = g_boff[blockIdx.x] + sh[t] - v;
}

__global__ void k_fill(const void* __restrict__ ei) {
    int i = blockIdx.x * blockDim.x + threadIdx.x;
    if (i >= ENT) return;
    int s, d;
    if (i < EE) { s = load_idx(ei, i); d = load_idx(ei, (long long)EE + i); }
    else        { s = d = i - EE; }
    int pos = atomicAdd(&g_cursor[d], 1);
    int idx = g_rowptr[d] + pos;
    g_col[idx] = s;
    g_w[idx]   = g_dinv[s] * g_dinv[d];
}

// ---------------- converters ----------------
__device__ __forceinline__ unsigned pack_fp8x4(float a, float b, float c, float d) {
    __nv_fp8x2_storage_t lo = __nv_cvt_float2_to_fp8x2(make_float2(a, b), __NV_SATFINITE, __NV_E4M3);
    __nv_fp8x2_storage_t hi = __nv_cvt_float2_to_fp8x2(make_float2(c, d), __NV_SATFINITE, __NV_E4M3);
    return (unsigned)lo | ((unsigned)hi << 16);
}
__device__ __forceinline__ float4 unpack_fp8x4(unsigned v) {
    __half2_raw ha = __nv_cvt_fp8x2_to_halfraw2((__nv_fp8x2_storage_t)(v & 0xFFFF), __NV_E4M3);
    __half2_raw hb = __nv_cvt_fp8x2_to_halfraw2((__nv_fp8x2_storage_t)(v >> 16), __NV_E4M3);
    float2 fa = __half22float2(ha), fb = __half22float2(hb);
    return make_float4(fa.x, fa.y, fb.x, fb.y);
}

// x fp32 -> e4m3 (g_X8)
__global__ __launch_bounds__(256) void k_cvt8x(const float* __restrict__ src, int n4) {
    int i = blockIdx.x * blockDim.x + threadIdx.x;
    if (i >= n4) return;
    float4 v = ((const float4*)src)[i];
    ((unsigned*)g_X8)[i] = pack_fp8x4(v.x, v.y, v.z, v.w);
}

// W fp32 [K][HH] -> e4m3 transposed g_W8t [HH][K] (k contiguous)
template<int K>
__global__ __launch_bounds__(256) void k_cvt8w(const float* __restrict__ src) {
    int idx = blockIdx.x * blockDim.x + threadIdx.x;     // over HH * (K/4)
    if (idx >= HH * (K / 4)) return;
    int n  = idx / (K / 4);
    int k  = (idx % (K / 4)) * 4;
    float a = src[(k + 0) * HH + n];
    float b = src[(k + 1) * HH + n];
    float c = src[(k + 2) * HH + n];
    float d = src[(k + 3) * HH + n];
    *(unsigned*)(g_W8t + (size_t)n * K + k) = pack_fp8x4(a, b, c, d);
}

// ---------------- fp8 tensor-core GEMM ----------------
// g_M8[N,256] = e4m3( A[N,K] @ W[K,256] ), A & W e4m3, fp32 accum, mma.m16n8k32.
__device__ __forceinline__ void ldsm_x4(unsigned* r, const void* p) {
    unsigned a = (unsigned)__cvta_generic_to_shared(p);
    asm volatile("ldmatrix.sync.aligned.m8n8.x4.shared.b16 {%0,%1,%2,%3}, [%4];"
                 : "=r"(r[0]), "=r"(r[1]), "=r"(r[2]), "=r"(r[3]) : "r"(a));
}
__device__ __forceinline__ void mma_fp8(float* c, const unsigned* a, const unsigned* b) {
    asm volatile("mma.sync.aligned.m16n8k32.row.col.f32.e4m3.e4m3.f32 "
                 "{%0,%1,%2,%3}, {%4,%5,%6,%7}, {%8,%9}, {%0,%1,%2,%3};"
                 : "+f"(c[0]), "+f"(c[1]), "+f"(c[2]), "+f"(c[3])
                 : "r"(a[0]), "r"(a[1]), "r"(a[2]), "r"(a[3]), "r"(b[0]), "r"(b[1]));
}

#define ASTR 80    // 64 fp8 + 16 pad (bytes per smem row)

// FIRST=true -> A = g_X8 (K=512); else A = g_H8 (K=256)
template<int K, bool FIRST>
__global__ __launch_bounds__(256) void k_gemm_fp8() {
    __shared__ unsigned char As[128 * ASTR];   // 128 m-rows x 64 k-fp8
    __shared__ unsigned char Bs[128 * ASTR];   // 128 n-rows x 64 k-fp8 (from W8t)

    int t      = threadIdx.x;
    int lane   = t & 31;
    int wid    = t >> 5;
    int warp_m = wid >> 2;       // 0..1 -> 64-row band
    int warp_n = wid & 3;        // 0..3 -> 32-col band
    int col0   = blockIdx.x * 128;
    int row0   = blockIdx.y * 128;

    const unsigned char* A = FIRST ? g_X8 : g_H8;

    float acc[4][4][4];
    #pragma unroll
    for (int mt = 0; mt < 4; mt++)
        #pragma unroll
        for (int nt = 0; nt < 4; nt++)
            #pragma unroll
            for (int r = 0; r < 4; r++) acc[mt][nt][r] = 0.f;

    for (int k0 = 0; k0 < K; k0 += 64) {
        // ---- load A tile: 128 rows x 64 fp8 = 512 uint4 ----
        #pragma unroll
        for (int u = 0; u < 2; u++) {
            int idx = t + u * 256;
            int m   = idx >> 2;          // 0..127
            int q   = idx & 3;           // 16B chunk
            int gr  = row0 + m;
            uint4 v = make_uint4(0u, 0u, 0u, 0u);
            if (gr < NN)
                v = *(const uint4*)(A + (size_t)gr * K + k0 + q * 16);
            *(uint4*)(As + m * ASTR + q * 16) = v;
        }
        // ---- load B tile: 128 n-rows x 64 fp8 from W8t[n][k] ----
        #pragma unroll
        for (int u = 0; u < 2; u++) {
            int idx = t + u * 256;
            int n   = idx >> 2;
            int q   = idx & 3;
            *(uint4*)(Bs + n * ASTR + q * 16) =
                *(const uint4*)(g_W8t + (size_t)(col0 + n) * K + k0 + q * 16);
        }
        __syncthreads();

        #pragma unroll
        for (int ks = 0; ks < 2; ks++) {     // two k32 mma steps per 64-fp8 chunk
            unsigned aF[4][4], bF[4][2];
            // A fragments: 16 rows x 32 fp8, ldmatrix x4 (b16-pair trick)
            int ar = lane & 15;
            int ac = (lane >> 4) * 16;       // 16B half select
            #pragma unroll
            for (int mt = 0; mt < 4; mt++)
                ldsm_x4(aF[mt], As + (warp_m * 64 + mt * 16 + ar) * ASTR + ks * 32 + ac);
            // B fragments: per pair p, 16 n-rows x 32 fp8 -> 2 nt tiles x {b0,b1}
            int bg = lane >> 3;              // matrix group 0..3
            #pragma unroll
            for (int p = 0; p < 2; p++) {
                int nrow = warp_n * 32 + p * 16 + (bg >> 1) * 8 + (lane & 7);
                unsigned tmp[4];
                ldsm_x4(tmp, Bs + nrow * ASTR + ks * 32 + (bg & 1) * 16);
                bF[p * 2][0]     = tmp[0];   // (n 0-7,  k 0-15)
                bF[p * 2][1]     = tmp[1];   // (n 0-7,  k 16-31)
                bF[p * 2 + 1][0] = tmp[2];   // (n 8-15, k 0-15)
                bF[p * 2 + 1][1] = tmp[3];   // (n 8-15, k 16-31)
            }
            #pragma unroll
            for (int mt = 0; mt < 4; mt++)
                #pragma unroll
                for (int nt = 0; nt < 4; nt++)
                    mma_fp8(acc[mt][nt], aF[mt], bF[nt]);
        }
        __syncthreads();
    }

    // epilogue: e4m3 store to g_M8
    #pragma unroll
    for (int mt = 0; mt < 4; mt++) {
        int gr0 = row0 + warp_m * 64 + mt * 16 + (lane >> 2);
        #pragma unroll
        for (int nt = 0; nt < 4; nt++) {
            int gc = col0 + warp_n * 32 + nt * 8 + (lane & 3) * 2;
            if (gr0 < NN) {
                __nv_fp8x2_storage_t p01 = __nv_cvt_float2_to_fp8x2(
                    make_float2(acc[mt][nt][0], acc[mt][nt][1]), __NV_SATFINITE, __NV_E4M3);
                *(unsigned short*)(g_M8 + (size_t)gr0 * HH + gc) = p01;
            }
            if (gr0 + 8 < NN) {
                __nv_fp8x2_storage_t p23 = __nv_cvt_float2_to_fp8x2(
                    make_float2(acc[mt][nt][2], acc[mt][nt][3]), __NV_SATFINITE, __NV_E4M3);
                *(unsigned short*)(g_M8 + (size_t)(gr0 + 8) * HH + gc) = p23;
            }
        }
    }
}

// ---------------- CSR gather aggregation (e4m3 in, e4m3 out, fp32 accum) ----------------
// one block per dst node; 64 threads, each owns 4 columns (one 4-byte fp8 quad)
template<int DO_RELU>
__global__ __launch_bounds__(64) void k_agg(const float* __restrict__ bias) {
    int n  = blockIdx.x;
    int c4 = threadIdx.x;            // 0..63 -> cols [4c4, 4c4+3]
    int start = g_rowptr[n];
    int end   = g_rowptr[n + 1];
    __shared__ int   scol[64];
    __shared__ float sw[64];
    const unsigned* m = (const unsigned*)g_M8;
    float4 a0 = make_float4(0.f, 0.f, 0.f, 0.f), a1 = a0;
    for (int e0 = start; e0 < end; e0 += 64) {
        int cnt = min(64, end - e0);
        if (c4 < cnt) { scol[c4] = g_col[e0 + c4]; sw[c4] = g_w[e0 + c4]; }
        __syncthreads();
        int j = 0;
        for (; j + 2 <= cnt; j += 2) {
            unsigned v0 = __ldg(m + (size_t)scol[j + 0] * 64 + c4);
            unsigned v1 = __ldg(m + (size_t)scol[j + 1] * 64 + c4);
            float w0 = sw[j + 0], w1 = sw[j + 1];
            float4 f0 = unpack_fp8x4(v0);
            float4 f1 = unpack_fp8x4(v1);
            a0.x = fmaf(f0.x, w0, a0.x); a0.y = fmaf(f0.y, w0, a0.y);
            a0.z = fmaf(f0.z, w0, a0.z); a0.w = fmaf(f0.w, w0, a0.w);
            a1.x = fmaf(f1.x, w1, a1.x); a1.y = fmaf(f1.y, w1, a1.y);
            a1.z = fmaf(f1.z, w1, a1.z); a1.w = fmaf(f1.w, w1, a1.w);
        }
        for (; j < cnt; j++) {
            unsigned v = __ldg(m + (size_t)scol[j] * 64 + c4);
            float w = sw[j];
            float4 f = unpack_fp8x4(v);
            a0.x = fmaf(f.x, w, a0.x); a0.y = fmaf(f.y, w, a0.y);
            a0.z = fmaf(f.z, w, a0.z); a0.w = fmaf(f.w, w, a0.w);
        }
        __syncthreads();
    }
    float r0 = a0.x + a1.x + bias[4 * c4 + 0];
    float r1 = a0.y + a1.y + bias[4 * c4 + 1];
    float r2 = a0.z + a1.z + bias[4 * c4 + 2];
    float r3 = a0.w + a1.w + bias[4 * c4 + 3];
    if (DO_RELU) {
        r0 = fmaxf(r0, 0.f); r1 = fmaxf(r1, 0.f);
        r2 = fmaxf(r2, 0.f); r3 = fmaxf(r3, 0.f);
    }
    *(unsigned*)(g_H8 + (size_t)n * HH + 4 * c4) = pack_fp8x4(r0, r1, r2, r3);
}

// ---------------- pooling ----------------
__global__ void k_zero_pool() {
    int i = blockIdx.x * blockDim.x + threadIdx.x;
    if (i < GG * HH) g_pooled[i] = 0.f;
    if (i < GG) g_gcount[i] = 0;
}

// block = 64 nodes x 64 col-quads; batch sorted -> few boundaries per chunk
__global__ __launch_bounds__(64) void k_pool(const void* __restrict__ batch) {
    int base = blockIdx.x * 64;
    int c4 = threadIdx.x;
    __shared__ int sg[64];
    int nmax = min(64, NN - base);
    if (nmax <= 0) return;
    if (c4 < nmax) sg[c4] = load_gidx(batch, base + c4);
    __syncthreads();
    const unsigned* h = (const unsigned*)g_H8;
    int gprev = sg[0];
    float4 acc = make_float4(0.f, 0.f, 0.f, 0.f);
    for (int i = 0; i < nmax; i++) {
        int g = sg[i];
        if (g != gprev) {
            atomicAdd(&g_pooled[gprev * HH + 4 * c4 + 0], acc.x);
            atomicAdd(&g_pooled[gprev * HH + 4 * c4 + 1], acc.y);
            atomicAdd(&g_pooled[gprev * HH + 4 * c4 + 2], acc.z);
            atomicAdd(&g_pooled[gprev * HH + 4 * c4 + 3], acc.w);
            acc = make_float4(0.f, 0.f, 0.f, 0.f);
            gprev = g;
        }
        float4 v = unpack_fp8x4(h[(size_t)(base + i) * 64 + c4]);
        acc.x += v.x; acc.y += v.y; acc.z += v.z; acc.w += v.w;
    }
    atomicAdd(&g_pooled[gprev * HH + 4 * c4 + 0], acc.x);
    atomicAdd(&g_pooled[gprev * HH + 4 * c4 + 1], acc.y);
    atomicAdd(&g_pooled[gprev * HH + 4 * c4 + 2], acc.z);
    atomicAdd(&g_pooled[gprev * HH + 4 * c4 + 3], acc.w);
    if (c4 < nmax) atomicAdd(&g_gcount[sg[c4]], 1);
}

// ---------------- final MLP + sigmoid ----------------
__global__ __launch_bounds__(1024) void k_mlp(const float* __restrict__ Wf,
                                              const float* __restrict__ bf,
                                              const float* __restrict__ Wp,
                                              const float* __restrict__ bp,
                                              float* __restrict__ out) {
    __shared__ float pm[GG * HH];
    __shared__ float fsh[GG * 64];
    int t = threadIdx.x;
    for (int i = t; i < GG * HH; i += 1024) {
        int g = i / HH;
        float cnt = fmaxf((float)g_gcount[g], 1.f);
        pm[i] = g_pooled[i] / cnt;
    }
    __syncthreads();
    int g  = t >> 6;
    int oc = t & 63;
    float f = bf[oc];
    #pragma unroll 8
    for (int k = 0; k < HH; k++)
        f = fmaf(pm[g * HH + k], Wf[k * 64 + oc], f);
    fsh[g * 64 + oc] = f;
    __syncthreads();
    if (t < GG) {
        float o = bp[0];
        #pragma unroll
        for (int j = 0; j < 64; j++)
            o = fmaf(fsh[t * 64 + j], Wp[j], o);
        out[t] = 1.f / (1.f + expf(-o));
    }
}

// ---------------- launch ----------------
extern "C" void kernel_launch(void* const* d_in, const int* in_sizes, int n_in,
                              void* d_out, int out_size) {
    const float* x     = (const float*)d_in[0];
    const void*  ei    = d_in[1];   // [2, E] int32 or int64 (probed on device)
    const void*  batch = d_in[2];
    const float* W1 = (const float*)d_in[3];
    const float* b1 = (const float*)d_in[4];
    const float* W2 = (const float*)d_in[5];
    const float* b2 = (const float*)d_in[6];
    const float* W3 = (const float*)d_in[7];
    const float* b3 = (const float*)d_in[8];
    const float* Wf = (const float*)d_in[9];
    const float* bf = (const float*)d_in[10];
    const float* Wp = (const float*)d_in[11];
    const float* bp = (const float*)d_in[12];
    float* out = (float*)d_out;

    // graph setup
    k_probe<<<1, 256>>>((const unsigned int*)ei);
    k_init_cnt<<<SCAN_B, 256>>>();
    k_count<<<(EE + 255) / 256, 256>>>(ei);
    k_dinv<<<SCAN_B, 256>>>();
    k_scan1<<<SCAN_B, 256>>>();
    k_scan2<<<1, 256>>>();
    k_scan3<<<SCAN_B, 256>>>();
    k_fill<<<(ENT + 255) / 256, 256>>>(ei);

    dim3 ggrid(2, (NN + 127) / 128);
    const int nA1 = NN * DIN / 4;

    k_cvt8x<<<(nA1 + 255) / 256, 256>>>(x, nA1);

    // layer 1
    k_cvt8w<DIN><<<(HH * (DIN / 4) + 255) / 256, 256>>>(W1);
    k_gemm_fp8<DIN, true><<<ggrid, 256>>>();
    k_agg<1><<<NN, 64>>>(b1);
    // layer 2
    k_cvt8w<HH><<<(HH * (HH / 4) + 255) / 256, 256>>>(W2);
    k_gemm_fp8<HH, false><<<ggrid, 256>>>();
    k_agg<1><<<NN, 64>>>(b2);
    // layer 3
    k_cvt8w<HH><<<(HH * (HH / 4) + 255) / 256, 256>>>(W3);
    k_gemm_fp8<HH, false><<<ggrid, 256>>>();
    k_agg<0><<<NN, 64>>>(b3);

    // pooling + head
    k_zero_pool<<<(GG * HH + 255) / 256, 256>>>();
    k_pool<<<(NN + 63) / 64, 64>>>(batch);
    k_mlp<<<1, 1024>>>(Wf, bf, Wp, bp, out);
}

// round 13
// speedup vs baseline: 1.0597x; 1.0597x over previous
#include <cuda_runtime.h>
#include <cuda_bf16.h>
#include <cuda_fp16.h>
#include <cuda_fp8.h>
#include <math.h>

// Problem constants (from reference_code)
#define NN   50000
#define EE   1600000
#define ENT  (EE + NN)     // edges incl. self-loops = 1650000
#define DIN  512
#define HH   256
#define GG   16
#define SCAN_B ((NN + 255) / 256)   // 196 scan blocks

// ---------------- device scratch (static; no allocation allowed) ----------------
__device__ int   g_is64;                    // 1 if indices are int64, 0 if int32
__device__ int   g_cnt[NN];
__device__ float g_dinv[NN];
__device__ int   g_rowptr[NN + 1];
__device__ int   g_cursor[NN];
__device__ int   g_bsum[SCAN_B];            // per-block partial sums
__device__ int   g_col[ENT];
__device__ float g_w[ENT];
__device__ float g_pooled[GG * HH];
__device__ int   g_gcount[GG];
// buffers
__device__ __align__(256) unsigned char g_M8[(size_t)NN * HH];   // GEMM out, e4m3 (gather in)
__device__ __nv_bfloat16 g_H16[(size_t)NN * HH];                 // agg out (next layer A)

// dtype-agnostic index load (flag-steered), clamped for crash-safety
__device__ __forceinline__ int load_idx(const void* p, long long i) {
    int v;
    if (g_is64) v = (int)((const long long*)p)[i];
    else        v = ((const int*)p)[i];
    return min(max(v, 0), NN - 1);
}
__device__ __forceinline__ int load_gidx(const void* p, long long i) {
    int v;
    if (g_is64) v = (int)((const long long*)p)[i];
    else        v = ((const int*)p)[i];
    return min(max(v, 0), GG - 1);
}

__device__ __forceinline__ float4 unpack_fp8x4(unsigned v) {
    __half2_raw ha = __nv_cvt_fp8x2_to_halfraw2((__nv_fp8x2_storage_t)(v & 0xFFFF), __NV_E4M3);
    __half2_raw hb = __nv_cvt_fp8x2_to_halfraw2((__nv_fp8x2_storage_t)(v >> 16), __NV_E4M3);
    float2 fa = __half22float2(ha), fb = __half22float2(hb);
    return make_float4(fa.x, fa.y, fb.x, fb.y);
}

// ---------------- fused setup0: probe dtype + init cnt + zero pool ----------------
__global__ void k_setup0(const unsigned int* __restrict__ w) {
    int gi = blockIdx.x * 256 + threadIdx.x;
    if (gi < NN) g_cnt[gi] = 1;                 // self-loop
    if (gi < GG * HH) g_pooled[gi] = 0.f;
    if (gi < GG) g_gcount[gi] = 0;
    if (blockIdx.x == 0) {                      // dtype probe (block 0 only)
        __shared__ int any;
        if (threadIdx.x == 0) any = 0;
        __syncthreads();
        for (int i = threadIdx.x; i < 2048; i += 256)
            if (w[2 * i + 1] != 0u) atomicOr(&any, 1);
        __syncthreads();
        if (threadIdx.x == 0) g_is64 = (any == 0) ? 1 : 0;
    }
}

__global__ void k_count(const void* __restrict__ ei) {
    int i = blockIdx.x * blockDim.x + threadIdx.x;
    if (i < EE) atomicAdd(&g_cnt[load_idx(ei, (long long)EE + i)], 1);
}

// fused: dinv + cursor init + per-block reduce of cnt -> bsum
__global__ void k_scan1f() {
    __shared__ int sh[256];
    int t = threadIdx.x;
    int i = blockIdx.x * 256 + t;
    int v = 0;
    if (i < NN) {
        v = g_cnt[i];
        g_dinv[i]   = rsqrtf((float)v);
        g_cursor[i] = 0;
    }
    sh[t] = v;
    __syncthreads();
    #pragma unroll
    for (int off = 128; off > 0; off >>= 1) {
        if (t < off) sh[t] += sh[t + off];
        __syncthreads();
    }
    if (t == 0) g_bsum[blockIdx.x] = sh[0];
}

// fused scan2+scan3: every block re-scans the 196 partials, then local scan
__global__ void k_scan23f() {
    __shared__ int sb[256];
    __shared__ int sh[256];
    int t = threadIdx.x;
    int vb = (t < SCAN_B) ? g_bsum[t] : 0;
    sb[t] = vb;
    __syncthreads();
    #pragma unroll
    for (int off = 1; off < 256; off <<= 1) {
        int tv = (t >= off) ? sb[t - off] : 0;
        __syncthreads();
        sb[t] += tv;
        __syncthreads();
    }
    int blk_off = sb[blockIdx.x] - g_bsum[blockIdx.x];   // exclusive offset of this block
    if (blockIdx.x == 0 && t == 255) g_rowptr[NN] = sb[255];
    // local scan
    int i = blockIdx.x * 256 + t;
    int v = (i < NN) ? g_cnt[i] : 0;
    sh[t] = v;
    __syncthreads();
    #pragma unroll
    for (int off = 1; off < 256; off <<= 1) {
        int tv = (t >= off) ? sh[t - off] : 0;
        __syncthreads();
        sh[t] += tv;
        __syncthreads();
    }
    if (i < NN) g_rowptr[i] = blk_off + sh[t] - v;
}

__global__ void k_fill(const void* __restrict__ ei) {
    int i = blockIdx.x * blockDim.x + threadIdx.x;
    if (i >= ENT) return;
    int s, d;
    if (i < EE) { s = load_idx(ei, i); d = load_idx(ei, (long long)EE + i); }
    else        { s = d = i - EE; }
    int pos = atomicAdd(&g_cursor[d], 1);
    int idx = g_rowptr[d] + pos;
    g_col[idx] = s;
    g_w[idx]   = g_dinv[s] * g_dinv[d];
}

// ---------------- tensor-core GEMM (bf16 MMA, in-kernel fp32->bf16 cvt) ----------------
// g_M8[N,256] = e4m3( A[N,K] @ W[K,256] ); A: fp32 x (FIRST) or bf16 H16; W: fp32 direct.
__device__ __forceinline__ void ldsm_x4(unsigned* r, const void* p) {
    unsigned a = (unsigned)__cvta_generic_to_shared(p);
    asm volatile("ldmatrix.sync.aligned.m8n8.x4.shared.b16 {%0,%1,%2,%3}, [%4];"
                 : "=r"(r[0]), "=r"(r[1]), "=r"(r[2]), "=r"(r[3]) : "r"(a));
}
__device__ __forceinline__ void ldsm_x4t(unsigned* r, const void* p) {
    unsigned a = (unsigned)__cvta_generic_to_shared(p);
    asm volatile("ldmatrix.sync.aligned.m8n8.x4.trans.shared.b16 {%0,%1,%2,%3}, [%4];"
                 : "=r"(r[0]), "=r"(r[1]), "=r"(r[2]), "=r"(r[3]) : "r"(a));
}
__device__ __forceinline__ void mma_bf16(float* c, const unsigned* a, const unsigned* b) {
    asm volatile("mma.sync.aligned.m16n8k16.row.col.f32.bf16.bf16.f32 "
                 "{%0,%1,%2,%3}, {%4,%5,%6,%7}, {%8,%9}, {%0,%1,%2,%3};"
                 : "+f"(c[0]), "+f"(c[1]), "+f"(c[2]), "+f"(c[3])
                 : "r"(a[0]), "r"(a[1]), "r"(a[2]), "r"(a[3]), "r"(b[0]), "r"(b[1]));
}

#define ASTRIDE 40    // 32 + 8 pad (bf16)
#define BSTRIDE 136   // 128 + 8 pad (bf16)

// FIRST=true -> A = x fp32 (K=512, convert on load); else A = g_H16 bf16 (K=256)
template<int K, bool FIRST>
__global__ __launch_bounds__(256) void k_gemm_mma(const float* __restrict__ Ax,
                                                  const float* __restrict__ W) {
    __shared__ __nv_bfloat16 As[128 * ASTRIDE];
    __shared__ __nv_bfloat16 Bs[32 * BSTRIDE];

    int t      = threadIdx.x;
    int lane   = t & 31;
    int wid    = t >> 5;
    int warp_m = wid >> 2;       // 0..1 -> 64-row band
    int warp_n = wid & 3;        // 0..3 -> 32-col band
    int col0   = blockIdx.x * 128;
    int row0   = blockIdx.y * 128;

    float acc[4][4][4];
    #pragma unroll
    for (int mt = 0; mt < 4; mt++)
        #pragma unroll
        for (int nt = 0; nt < 4; nt++)
            #pragma unroll
            for (int r = 0; r < 4; r++) acc[mt][nt][r] = 0.f;

    for (int k0 = 0; k0 < K; k0 += 32) {
        // ---- load A tile: 128 rows x 32 (cvt fp32->bf16 if FIRST) ----
        if (FIRST) {
            #pragma unroll
            for (int u = 0; u < 4; u++) {
                int idx = t + u * 256;       // 0..1023
                int m   = idx >> 3;          // 0..127
                int q   = idx & 7;           // float4 within 32-k row
                int gr  = row0 + m;
                float4 v = make_float4(0.f, 0.f, 0.f, 0.f);
                if (gr < NN)
                    v = *(const float4*)(Ax + (size_t)gr * K + k0 + q * 4);
                __nv_bfloat162* p = (__nv_bfloat162*)(As + m * ASTRIDE + q * 4);
                p[0] = __floats2bfloat162_rn(v.x, v.y);
                p[1] = __floats2bfloat162_rn(v.z, v.w);
            }
        } else {
            #pragma unroll
            for (int u = 0; u < 2; u++) {
                int idx = t + u * 256;
                int m   = idx >> 2;
                int q   = idx & 3;
                int gr  = row0 + m;
                uint4 v = make_uint4(0u, 0u, 0u, 0u);
                if (gr < NN)
                    v = *(const uint4*)(g_H16 + (size_t)gr * K + k0 + q * 8);
                *(uint4*)(As + m * ASTRIDE + q * 8) = v;
            }
        }
        // ---- load B tile: 32 k-rows x 128 cols fp32 -> bf16 smem ----
        #pragma unroll
        for (int u = 0; u < 4; u++) {
            int idx = t + u * 256;           // 0..1023
            int kk  = idx >> 5;              // 0..31
            int q   = idx & 31;              // float4 within 128-col slice
            float4 v = *(const float4*)(W + (size_t)(k0 + kk) * HH + col0 + q * 4);
            __nv_bfloat162* p = (__nv_bfloat162*)(Bs + kk * BSTRIDE + q * 4);
            p[0] = __floats2bfloat162_rn(v.x, v.y);
            p[1] = __floats2bfloat162_rn(v.z, v.w);
        }
        __syncthreads();

        #pragma unroll
        for (int ks = 0; ks < 2; ks++) {
            unsigned ah[4][4], bh[4][2];
            int ar = lane & 15;
            int ac = (lane >> 4) * 8;
            #pragma unroll
            for (int mt = 0; mt < 4; mt++)
                ldsm_x4(ah[mt], As + (warp_m * 64 + mt * 16 + ar) * ASTRIDE + ks * 16 + ac);
            int bg  = lane >> 3;
            int brw = ks * 16 + (bg & 1) * 8 + (lane & 7);
            #pragma unroll
            for (int p = 0; p < 2; p++) {
                int bc = warp_n * 32 + p * 16 + (bg >> 1) * 8;
                unsigned tmp[4];
                ldsm_x4t(tmp, Bs + brw * BSTRIDE + bc);
                bh[p * 2][0] = tmp[0]; bh[p * 2][1] = tmp[1];
                bh[p * 2 + 1][0] = tmp[2]; bh[p * 2 + 1][1] = tmp[3];
            }
            #pragma unroll
            for (int mt = 0; mt < 4; mt++)
                #pragma unroll
                for (int nt = 0; nt < 4; nt++)
                    mma_bf16(acc[mt][nt], ah[mt], bh[nt]);
        }
        __syncthreads();
    }

    // epilogue: e4m3 store to g_M8
    #pragma unroll
    for (int mt = 0; mt < 4; mt++) {
        int gr0 = row0 + warp_m * 64 + mt * 16 + (lane >> 2);
        #pragma unroll
        for (int nt = 0; nt < 4; nt++) {
            int gc = col0 + warp_n * 32 + nt * 8 + (lane & 3) * 2;
            if (gr0 < NN) {
                __nv_fp8x2_storage_t p01 = __nv_cvt_float2_to_fp8x2(
                    make_float2(acc[mt][nt][0], acc[mt][nt][1]), __NV_SATFINITE, __NV_E4M3);
                *(unsigned short*)(g_M8 + (size_t)gr0 * HH + gc) = p01;
            }
            if (gr0 + 8 < NN) {
                __nv_fp8x2_storage_t p23 = __nv_cvt_float2_to_fp8x2(
                    make_float2(acc[mt][nt][2], acc[mt][nt][3]), __NV_SATFINITE, __NV_E4M3);
                *(unsigned short*)(g_M8 + (size_t)(gr0 + 8) * HH + gc) = p23;
            }
        }
    }
}

// ---------------- CSR gather aggregation (e4m3 in, bf16 out, fp32 accum) ----------------
// one block per dst node; 64 threads, each owns 4 columns (one 4-byte fp8 quad)
template<int DO_RELU>
__global__ __launch_bounds__(64) void k_agg(const float* __restrict__ bias) {
    int n  = blockIdx.x;
    int c4 = threadIdx.x;            // 0..63 -> cols [4c4, 4c4+3]
    int start = g_rowptr[n];
    int end   = g_rowptr[n + 1];
    __shared__ int   scol[64];
    __shared__ float sw[64];
    const unsigned* m = (const unsigned*)g_M8;
    float4 a0 = make_float4(0.f, 0.f, 0.f, 0.f), a1 = a0;
    for (int e0 = start; e0 < end; e0 += 64) {
        int cnt = min(64, end - e0);
        if (c4 < cnt) { scol[c4] = g_col[e0 + c4]; sw[c4] = g_w[e0 + c4]; }
        __syncthreads();
        int j = 0;
        for (; j + 2 <= cnt; j += 2) {
            unsigned v0 = __ldg(m + (size_t)scol[j + 0] * 64 + c4);
            unsigned v1 = __ldg(m + (size_t)scol[j + 1] * 64 + c4);
            float w0 = sw[j + 0], w1 = sw[j + 1];
            float4 f0 = unpack_fp8x4(v0);
            float4 f1 = unpack_fp8x4(v1);
            a0.x = fmaf(f0.x, w0, a0.x); a0.y = fmaf(f0.y, w0, a0.y);
            a0.z = fmaf(f0.z, w0, a0.z); a0.w = fmaf(f0.w, w0, a0.w);
            a1.x = fmaf(f1.x, w1, a1.x); a1.y = fmaf(f1.y, w1, a1.y);
            a1.z = fmaf(f1.z, w1, a1.z); a1.w = fmaf(f1.w, w1, a1.w);
        }
        for (; j < cnt; j++) {
            unsigned v = __ldg(m + (size_t)scol[j] * 64 + c4);
            float w = sw[j];
            float4 f = unpack_fp8x4(v);
            a0.x = fmaf(f.x, w, a0.x); a0.y = fmaf(f.y, w, a0.y);
            a0.z = fmaf(f.z, w, a0.z); a0.w = fmaf(f.w, w, a0.w);
        }
        __syncthreads();
    }
    float r0 = a0.x + a1.x + bias[4 * c4 + 0];
    float r1 = a0.y + a1.y + bias[4 * c4 + 1];
    float r2 = a0.z + a1.z + bias[4 * c4 + 2];
    float r3 = a0.w + a1.w + bias[4 * c4 + 3];
    if (DO_RELU) {
        r0 = fmaxf(r0, 0.f); r1 = fmaxf(r1, 0.f);
        r2 = fmaxf(r2, 0.f); r3 = fmaxf(r3, 0.f);
    }
    __nv_bfloat162* hp = (__nv_bfloat162*)(g_H16 + (size_t)n * HH + 4 * c4);
    hp[0] = __floats2bfloat162_rn(r0, r1);
    hp[1] = __floats2bfloat162_rn(r2, r3);
}

// ---------------- pooling ----------------
// block = 64 nodes x 128 col-pairs; batch sorted -> few boundaries per chunk
__global__ __launch_bounds__(128) void k_pool(const void* __restrict__ batch) {
    int base = blockIdx.x * 64;
    int c2 = threadIdx.x;
    __shared__ int sg[64];
    int nmax = min(64, NN - base);
    if (nmax <= 0) return;
    if (c2 < nmax) sg[c2] = load_gidx(batch, base + c2);
    __syncthreads();
    const __nv_bfloat162* h = (const __nv_bfloat162*)g_H16;
    int gprev = sg[0];
    float2 acc = make_float2(0.f, 0.f);
    for (int i = 0; i < nmax; i++) {
        int g = sg[i];
        if (g != gprev) {
            atomicAdd(&g_pooled[gprev * HH + 2 * c2], acc.x);
            atomicAdd(&g_pooled[gprev * HH + 2 * c2 + 1], acc.y);
            acc = make_float2(0.f, 0.f);
            gprev = g;
        }
        float2 v = __bfloat1622float2(h[(size_t)(base + i) * 128 + c2]);
        acc.x += v.x; acc.y += v.y;
    }
    atomicAdd(&g_pooled[gprev * HH + 2 * c2], acc.x);
    atomicAdd(&g_pooled[gprev * HH + 2 * c2 + 1], acc.y);
    if (c2 < nmax) atomicAdd(&g_gcount[sg[c2]], 1);
}

// ---------------- final MLP + sigmoid ----------------
__global__ __launch_bounds__(1024) void k_mlp(const float* __restrict__ Wf,
                                              const float* __restrict__ bf,
                                              const float* __restrict__ Wp,
                                              const float* __restrict__ bp,
                                              float* __restrict__ out) {
    __shared__ float pm[GG * HH];
    __shared__ float fsh[GG * 64];
    int t = threadIdx.x;
    for (int i = t; i < GG * HH; i += 1024) {
        int g = i / HH;
        float cnt = fmaxf((float)g_gcount[g], 1.f);
        pm[i] = g_pooled[i] / cnt;
    }
    __syncthreads();
    int g  = t >> 6;
    int oc = t & 63;
    float f = bf[oc];
    #pragma unroll 8
    for (int k = 0; k < HH; k++)
        f = fmaf(pm[g * HH + k], Wf[k * 64 + oc], f);
    fsh[g * 64 + oc] = f;
    __syncthreads();
    if (t < GG) {
        float o = bp[0];
        #pragma unroll
        for (int j = 0; j < 64; j++)
            o = fmaf(fsh[t * 64 + j], Wp[j], o);
        out[t] = 1.f / (1.f + expf(-o));
    }
}

// ---------------- launch ----------------
extern "C" void kernel_launch(void* const* d_in, const int* in_sizes, int n_in,
                              void* d_out, int out_size) {
    const float* x     = (const float*)d_in[0];
    const void*  ei    = d_in[1];   // [2, E] int32 or int64 (probed on device)
    const void*  batch = d_in[2];
    const float* W1 = (const float*)d_in[3];
    const float* b1 = (const float*)d_in[4];
    const float* W2 = (const float*)d_in[5];
    const float* b2 = (const float*)d_in[6];
    const float* W3 = (const float*)d_in[7];
    const float* b3 = (const float*)d_in[8];
    const float* Wf = (const float*)d_in[9];
    const float* bf = (const float*)d_in[10];
    const float* Wp = (const float*)d_in[11];
    const float* bp = (const float*)d_in[12];
    float* out = (float*)d_out;

    // graph setup (5 kernels)
    k_setup0<<<SCAN_B, 256>>>((const unsigned int*)ei);
    k_count<<<(EE + 255) / 256, 256>>>(ei);
    k_scan1f<<<SCAN_B, 256>>>();
    k_scan23f<<<SCAN_B, 256>>>();
    k_fill<<<(ENT + 255) / 256, 256>>>(ei);

    dim3 ggrid(2, (NN + 127) / 128);

    // layer 1 (A = x fp32, converted in-kernel)
    k_gemm_mma<DIN, true><<<ggrid, 256>>>(x, W1);
    k_agg<1><<<NN, 64>>>(b1);
    // layer 2
    k_gemm_mma<HH, false><<<ggrid, 256>>>(nullptr, W2);
    k_agg<1><<<NN, 64>>>(b2);
    // layer 3
    k_gemm_mma<HH, false><<<ggrid, 256>>>(nullptr, W3);
    k_agg<0><<<NN, 64>>>(b3);

    // pooling + head
    k_pool<<<(NN + 63) / 64, 128>>>(batch);
    k_mlp<<<1, 1024>>>(Wf, bf, Wp, bp, out);
}

// round 16
// speedup vs baseline: 1.1100x; 1.0475x over previous
#include <cuda_runtime.h>
#include <cuda_bf16.h>
#include <cuda_fp16.h>
#include <cuda_fp8.h>
#include <math.h>

// Problem constants (from reference_code)
#define NN   50000
#define EE   1600000
#define ENT  (EE + NN)     // edges incl. self-loops = 1650000
#define DIN  512
#define HH   256
#define GG   16
#define SCAN_B ((NN + 255) / 256)   // 196 scan blocks

// ---------------- device scratch (static; no allocation allowed) ----------------
__device__ int   g_is64;                    // 1 if indices are int64, 0 if int32
__device__ int   g_cnt[NN];
__device__ float g_dinv[NN];
__device__ int   g_rowptr[NN + 1];
__device__ int   g_cursor[NN];
__device__ int   g_bsum[SCAN_B];            // per-block partial sums
__device__ int   g_col[ENT];
__device__ float g_w[ENT];
__device__ float g_pooled[GG * HH];
__device__ int   g_gcount[GG];
// buffers
__device__ __align__(256) unsigned char g_M8[(size_t)NN * HH];   // GEMM out, e4m3 (gather in)
__device__ __nv_bfloat16 g_H16[(size_t)NN * HH];                 // agg out (next layer A)

// dtype-agnostic index load (flag-steered), clamped for crash-safety
__device__ __forceinline__ int load_idx(const void* p, long long i) {
    int v;
    if (g_is64) v = (int)((const long long*)p)[i];
    else        v = ((const int*)p)[i];
    return min(max(v, 0), NN - 1);
}
__device__ __forceinline__ int load_gidx(const void* p, long long i) {
    int v;
    if (g_is64) v = (int)((const long long*)p)[i];
    else        v = ((const int*)p)[i];
    return min(max(v, 0), GG - 1);
}

__device__ __forceinline__ float4 unpack_fp8x4(unsigned v) {
    __half2_raw ha = __nv_cvt_fp8x2_to_halfraw2((__nv_fp8x2_storage_t)(v & 0xFFFF), __NV_E4M3);
    __half2_raw hb = __nv_cvt_fp8x2_to_halfraw2((__nv_fp8x2_storage_t)(v >> 16), __NV_E4M3);
    float2 fa = __half22float2(ha), fb = __half22float2(hb);
    return make_float4(fa.x, fa.y, fb.x, fb.y);
}
__device__ __forceinline__ uint2 pack_bf16x4(float4 v) {
    __nv_bfloat162 lo = __floats2bfloat162_rn(v.x, v.y);
    __nv_bfloat162 hi = __floats2bfloat162_rn(v.z, v.w);
    uint2 r;
    r.x = *(unsigned*)&lo;
    r.y = *(unsigned*)&hi;
    return r;
}

// ---------------- fused setup0: probe dtype + init cnt + zero pool ----------------
__global__ void k_setup0(const unsigned int* __restrict__ w) {
    int gi = blockIdx.x * 256 + threadIdx.x;
    if (gi < NN) g_cnt[gi] = 1;                 // self-loop
    if (gi < GG * HH) g_pooled[gi] = 0.f;
    if (gi < GG) g_gcount[gi] = 0;
    if (blockIdx.x == 0) {                      // dtype probe (block 0 only)
        __shared__ int any;
        if (threadIdx.x == 0) any = 0;
        __syncthreads();
        for (int i = threadIdx.x; i < 2048; i += 256)
            if (w[2 * i + 1] != 0u) atomicOr(&any, 1);
        __syncthreads();
        if (threadIdx.x == 0) g_is64 = (any == 0) ? 1 : 0;
    }
}

__global__ void k_count(const void* __restrict__ ei) {
    int i = blockIdx.x * blockDim.x + threadIdx.x;
    if (i < EE) atomicAdd(&g_cnt[load_idx(ei, (long long)EE + i)], 1);
}

// fused: dinv + cursor init + per-block reduce of cnt -> bsum
__global__ void k_scan1f() {
    __shared__ int sh[256];
    int t = threadIdx.x;
    int i = blockIdx.x * 256 + t;
    int v = 0;
    if (i < NN) {
        v = g_cnt[i];
        g_dinv[i]   = rsqrtf((float)v);
        g_cursor[i] = 0;
    }
    sh[t] = v;
    __syncthreads();
    #pragma unroll
    for (int off = 128; off > 0; off >>= 1) {
        if (t < off) sh[t] += sh[t + off];
        __syncthreads();
    }
    if (t == 0) g_bsum[blockIdx.x] = sh[0];
}

// fused scan2+scan3: every block re-scans the 196 partials, then local scan
__global__ void k_scan23f() {
    __shared__ int sb[256];
    __shared__ int sh[256];
    int t = threadIdx.x;
    int vb = (t < SCAN_B) ? g_bsum[t] : 0;
    sb[t] = vb;
    __syncthreads();
    #pragma unroll
    for (int off = 1; off < 256; off <<= 1) {
        int tv = (t >= off) ? sb[t - off] : 0;
        __syncthreads();
        sb[t] += tv;
        __syncthreads();
    }
    int blk_off = sb[blockIdx.x] - g_bsum[blockIdx.x];   // exclusive offset of this block
    if (blockIdx.x == 0 && t == 255) g_rowptr[NN] = sb[255];
    // local scan
    int i = blockIdx.x * 256 + t;
    int v = (i < NN) ? g_cnt[i] : 0;
    sh[t] = v;
    __syncthreads();
    #pragma unroll
    for (int off = 1; off < 256; off <<= 1) {
        int tv = (t >= off) ? sh[t - off] : 0;
        __syncthreads();
        sh[t] += tv;
        __syncthreads();
    }
    if (i < NN) g_rowptr[i] = blk_off + sh[t] - v;
}

__global__ void k_fill(const void* __restrict__ ei) {
    int i = blockIdx.x * blockDim.x + threadIdx.x;
    if (i >= ENT) return;
    int s, d;
    if (i < EE) { s = load_idx(ei, i); d = load_idx(ei, (long long)EE + i); }
    else        { s = d = i - EE; }
    int pos = atomicAdd(&g_cursor[d], 1);
    int idx = g_rowptr[d] + pos;
    g_col[idx] = s;
    g_w[idx]   = g_dinv[s] * g_dinv[d];
}

// ---------------- pipelined tensor-core GEMM (bf16 MMA, reg-prefetch + dbl smem) ----------------
// g_M8[N,256] = e4m3( A[N,K] @ W[K,256] ); A: fp32 x (FIRST) or bf16 H16; W: fp32 direct.
__device__ __forceinline__ void ldsm_x4(unsigned* r, const void* p) {
    unsigned a = (unsigned)__cvta_generic_to_shared(p);
    asm volatile("ldmatrix.sync.aligned.m8n8.x4.shared.b16 {%0,%1,%2,%3}, [%4];"
                 : "=r"(r[0]), "=r"(r[1]), "=r"(r[2]), "=r"(r[3]) : "r"(a));
}
__device__ __forceinline__ void ldsm_x4t(unsigned* r, const void* p) {
    unsigned a = (unsigned)__cvta_generic_to_shared(p);
    asm volatile("ldmatrix.sync.aligned.m8n8.x4.trans.shared.b16 {%0,%1,%2,%3}, [%4];"
                 : "=r"(r[0]), "=r"(r[1]), "=r"(r[2]), "=r"(r[3]) : "r"(a));
}
__device__ __forceinline__ void mma_bf16(float* c, const unsigned* a, const unsigned* b) {
    asm volatile("mma.sync.aligned.m16n8k16.row.col.f32.bf16.bf16.f32 "
                 "{%0,%1,%2,%3}, {%4,%5,%6,%7}, {%8,%9}, {%0,%1,%2,%3};"
                 : "+f"(c[0]), "+f"(c[1]), "+f"(c[2]), "+f"(c[3])
                 : "r"(a[0]), "r"(a[1]), "r"(a[2]), "r"(a[3]), "r"(b[0]), "r"(b[1]));
}

#define ASTRIDE 40    // 32 + 8 pad (bf16)
#define BSTRIDE 136   // 128 + 8 pad (bf16)

// FIRST=true -> A = x fp32 (K=512, convert on load); else A = g_H16 bf16 (K=256)
template<int K, bool FIRST>
__global__ __launch_bounds__(256) void k_gemm_mma(const float* __restrict__ Ax,
                                                  const float* __restrict__ W) {
    __shared__ __nv_bfloat16 As[2][128 * ASTRIDE];
    __shared__ __nv_bfloat16 Bs[2][32 * BSTRIDE];

    int t      = threadIdx.x;
    int lane   = t & 31;
    int wid    = t >> 5;
    int warp_m = wid >> 2;       // 0..1 -> 64-row band
    int warp_n = wid & 3;        // 0..3 -> 32-col band
    int col0   = blockIdx.x * 128;
    int row0   = blockIdx.y * 128;

    const int NCH = K / 32;

    float acc[4][4][4];
    #pragma unroll
    for (int mt = 0; mt < 4; mt++)
        #pragma unroll
        for (int nt = 0; nt < 4; nt++)
            #pragma unroll
            for (int r = 0; r < 4; r++) acc[mt][nt][r] = 0.f;

    // prefetch registers (converted to bf16 at load)
    uint2 pa[4];     // FIRST path: 4 x 8B chunks of A
    uint4 pa4[2];    // non-FIRST path: 2 x 16B chunks of A
    uint2 pb[4];     // 4 x 8B chunks of B

    // ---- prefetch chunk k0 into registers ----
    auto load_chunk = [&](int k0) {
        if (FIRST) {
            #pragma unroll
            for (int u = 0; u < 4; u++) {
                int idx = t + u * 256;       // 0..1023
                int m   = idx >> 3;          // 0..127
                int q   = idx & 7;           // float4 within 32-k row
                int gr  = row0 + m;
                float4 v = make_float4(0.f, 0.f, 0.f, 0.f);
                if (gr < NN)
                    v = *(const float4*)(Ax + (size_t)gr * K + k0 + q * 4);
                pa[u] = pack_bf16x4(v);
            }
        } else {
            #pragma unroll
            for (int u = 0; u < 2; u++) {
                int idx = t + u * 256;
                int m   = idx >> 2;
                int q   = idx & 3;
                int gr  = row0 + m;
                uint4 v = make_uint4(0u, 0u, 0u, 0u);
                if (gr < NN)
                    v = *(const uint4*)(g_H16 + (size_t)gr * K + k0 + q * 8);
                pa4[u] = v;
            }
        }
        #pragma unroll
        for (int u = 0; u < 4; u++) {
            int idx = t + u * 256;           // 0..1023
            int kk  = idx >> 5;              // 0..31
            int q   = idx & 31;              // float4 within 128-col slice
            float4 v = *(const float4*)(W + (size_t)(k0 + kk) * HH + col0 + q * 4);
            pb[u] = pack_bf16x4(v);
        }
    };

    // ---- store prefetched registers into smem buffer ----
    auto store_chunk = [&](int buf) {
        if (FIRST) {
            #pragma unroll
            for (int u = 0; u < 4; u++) {
                int idx = t + u * 256;
                int m   = idx >> 3;
                int q   = idx & 7;
                *(uint2*)(As[buf] + m * ASTRIDE + q * 4) = pa[u];
            }
        } else {
            #pragma unroll
            for (int u = 0; u < 2; u++) {
                int idx = t + u * 256;
                int m   = idx >> 2;
                int q   = idx & 3;
                *(uint4*)(As[buf] + m * ASTRIDE + q * 8) = pa4[u];
            }
        }
        #pragma unroll
        for (int u = 0; u < 4; u++) {
            int idx = t + u * 256;
            int kk  = idx >> 5;
            int q   = idx & 31;
            *(uint2*)(Bs[buf] + kk * BSTRIDE + q * 4) = pb[u];
        }
    };

    // prologue
    load_chunk(0);
    store_chunk(0);
    __syncthreads();

    int buf = 0;
    for (int ic = 0; ic < NCH; ic++) {
        if (ic + 1 < NCH) load_chunk((ic + 1) * 32);   // global loads overlap compute

        // ---- compute on smem[buf] ----
        #pragma unroll
        for (int ks = 0; ks < 2; ks++) {
            unsigned ah[4][4], bh[4][2];
            int ar = lane & 15;
            int ac = (lane >> 4) * 8;
            #pragma unroll
            for (int mt = 0; mt < 4; mt++)
                ldsm_x4(ah[mt], As[buf] + (warp_m * 64 + mt * 16 + ar) * ASTRIDE + ks * 16 + ac);
            int bg  = lane >> 3;
            int brw = ks * 16 + (bg & 1) * 8 + (lane & 7);
            #pragma unroll
            for (int p = 0; p < 2; p++) {
                int bc = warp_n * 32 + p * 16 + (bg >> 1) * 8;
                unsigned tmp[4];
                ldsm_x4t(tmp, Bs[buf] + brw * BSTRIDE + bc);
                bh[p * 2][0] = tmp[0]; bh[p * 2][1] = tmp[1];
                bh[p * 2 + 1][0] = tmp[2]; bh[p * 2 + 1][1] = tmp[3];
            }
            #pragma unroll
            for (int mt = 0; mt < 4; mt++)
                #pragma unroll
                for (int nt = 0; nt < 4; nt++)
                    mma_bf16(acc[mt][nt], ah[mt], bh[nt]);
        }

        if (ic + 1 < NCH) store_chunk(buf ^ 1);
        __syncthreads();
        buf ^= 1;
    }

    // epilogue: e4m3 store to g_M8
    #pragma unroll
    for (int mt = 0; mt < 4; mt++) {
        int gr0 = row0 + warp_m * 64 + mt * 16 + (lane >> 2);
        #pragma unroll
        for (int nt = 0; nt < 4; nt++) {
            int gc = col0 + warp_n * 32 + nt * 8 + (lane & 3) * 2;
            if (gr0 < NN) {
                __nv_fp8x2_storage_t p01 = __nv_cvt_float2_to_fp8x2(
                    make_float2(acc[mt][nt][0], acc[mt][nt][1]), __NV_SATFINITE, __NV_E4M3);
                *(unsigned short*)(g_M8 + (size_t)gr0 * HH + gc) = p01;
            }
            if (gr0 + 8 < NN) {
                __nv_fp8x2_storage_t p23 = __nv_cvt_float2_to_fp8x2(
                    make_float2(acc[mt][nt][2], acc[mt][nt][3]), __NV_SATFINITE, __NV_E4M3);
                *(unsigned short*)(g_M8 + (size_t)(gr0 + 8) * HH + gc) = p23;
            }
        }
    }
}

// ---------------- CSR gather aggregation (e4m3 in, bf16 out, fp32 accum) ----------------
// one block per dst node; 64 threads, each owns 4 columns (one 4-byte fp8 quad)
template<int DO_RELU>
__global__ __launch_bounds__(64) void k_agg(const float* __restrict__ bias) {
    int n  = blockIdx.x;
    int c4 = threadIdx.x;            // 0..63 -> cols [4c4, 4c4+3]
    int start = g_rowptr[n];
    int end   = g_rowptr[n + 1];
    __shared__ int   scol[64];
    __shared__ float sw[64];
    const unsigned* m = (const unsigned*)g_M8;
    float4 a0 = make_float4(0.f, 0.f, 0.f, 0.f), a1 = a0;
    for (int e0 = start; e0 < end; e0 += 64) {
        int cnt = min(64, end - e0);
        if (c4 < cnt) { scol[c4] = g_col[e0 + c4]; sw[c4] = g_w[e0 + c4]; }
        __syncthreads();
        int j = 0;
        for (; j + 2 <= cnt; j += 2) {
            unsigned v0 = __ldg(m + (size_t)scol[j + 0] * 64 + c4);
            unsigned v1 = __ldg(m + (size_t)scol[j + 1] * 64 + c4);
            float w0 = sw[j + 0], w1 = sw[j + 1];
            float4 f0 = unpack_fp8x4(v0);
            float4 f1 = unpack_fp8x4(v1);
            a0.x = fmaf(f0.x, w0, a0.x); a0.y = fmaf(f0.y, w0, a0.y);
            a0.z = fmaf(f0.z, w0, a0.z); a0.w = fmaf(f0.w, w0, a0.w);
            a1.x = fmaf(f1.x, w1, a1.x); a1.y = fmaf(f1.y, w1, a1.y);
            a1.z = fmaf(f1.z, w1, a1.z); a1.w = fmaf(f1.w, w1, a1.w);
        }
        for (; j < cnt; j++) {
            unsigned v = __ldg(m + (size_t)scol[j] * 64 + c4);
            float w = sw[j];
            float4 f = unpack_fp8x4(v);
            a0.x = fmaf(f.x, w, a0.x); a0.y = fmaf(f.y, w, a0.y);
            a0.z = fmaf(f.z, w, a0.z); a0.w = fmaf(f.w, w, a0.w);
        }
        __syncthreads();
    }
    float r0 = a0.x + a1.x + bias[4 * c4 + 0];
    float r1 = a0.y + a1.y + bias[4 * c4 + 1];
    float r2 = a0.z + a1.z + bias[4 * c4 + 2];
    float r3 = a0.w + a1.w + bias[4 * c4 + 3];
    if (DO_RELU) {
        r0 = fmaxf(r0, 0.f); r1 = fmaxf(r1, 0.f);
        r2 = fmaxf(r2, 0.f); r3 = fmaxf(r3, 0.f);
    }
    __nv_bfloat162* hp = (__nv_bfloat162*)(g_H16 + (size_t)n * HH + 4 * c4);
    hp[0] = __floats2bfloat162_rn(r0, r1);
    hp[1] = __floats2bfloat162_rn(r2, r3);
}

// ---------------- pooling ----------------
// block = 64 nodes x 128 col-pairs; batch sorted -> few boundaries per chunk
__global__ __launch_bounds__(128) void k_pool(const void* __restrict__ batch) {
    int base = blockIdx.x * 64;
    int c2 = threadIdx.x;
    __shared__ int sg[64];
    int nmax = min(64, NN - base);
    if (nmax <= 0) return;
    if (c2 < nmax) sg[c2] = load_gidx(batch, base + c2);
    __syncthreads();
    const __nv_bfloat162* h = (const __nv_bfloat162*)g_H16;
    int gprev = sg[0];
    float2 acc = make_float2(0.f, 0.f);
    for (int i = 0; i < nmax; i++) {
        int g = sg[i];
        if (g != gprev) {
            atomicAdd(&g_pooled[gprev * HH + 2 * c2], acc.x);
            atomicAdd(&g_pooled[gprev * HH + 2 * c2 + 1], acc.y);
            acc = make_float2(0.f, 0.f);
            gprev = g;
        }
        float2 v = __bfloat1622float2(h[(size_t)(base + i) * 128 + c2]);
        acc.x += v.x; acc.y += v.y;
    }
    atomicAdd(&g_pooled[gprev * HH + 2 * c2], acc.x);
    atomicAdd(&g_pooled[gprev * HH + 2 * c2 + 1], acc.y);
    if (c2 < nmax) atomicAdd(&g_gcount[sg[c2]], 1);
}

// ---------------- final MLP + sigmoid ----------------
__global__ __launch_bounds__(1024) void k_mlp(const float* __restrict__ Wf,
                                              const float* __restrict__ bf,
                                              const float* __restrict__ Wp,
                                              const float* __restrict__ bp,
                                              float* __restrict__ out) {
    __shared__ float pm[GG * HH];
    __shared__ float fsh[GG * 64];
    int t = threadIdx.x;
    for (int i = t; i < GG * HH; i += 1024) {
        int g = i / HH;
        float cnt = fmaxf((float)g_gcount[g], 1.f);
        pm[i] = g_pooled[i] / cnt;
    }
    __syncthreads();
    int g  = t >> 6;
    int oc = t & 63;
    float f = bf[oc];
    #pragma unroll 8
    for (int k = 0; k < HH; k++)
        f = fmaf(pm[g * HH + k], Wf[k * 64 + oc], f);
    fsh[g * 64 + oc] = f;
    __syncthreads();
    if (t < GG) {
        float o = bp[0];
        #pragma unroll
        for (int j = 0; j < 64; j++)
            o = fmaf(fsh[t * 64 + j], Wp[j], o);
        out[t] = 1.f / (1.f + expf(-o));
    }
}

// ---------------- launch ----------------
extern "C" void kernel_launch(void* const* d_in, const int* in_sizes, int n_in,
                              void* d_out, int out_size) {
    const float* x     = (const float*)d_in[0];
    const void*  ei    = d_in[1];   // [2, E] int32 or int64 (probed on device)
    const void*  batch = d_in[2];
    const float* W1 = (const float*)d_in[3];
    const float* b1 = (const float*)d_in[4];
    const float* W2 = (const float*)d_in[5];
    const float* b2 = (const float*)d_in[6];
    const float* W3 = (const float*)d_in[7];
    const float* b3 = (const float*)d_in[8];
    const float* Wf = (const float*)d_in[9];
    const float* bf = (const float*)d_in[10];
    const float* Wp = (const float*)d_in[11];
    const float* bp = (const float*)d_in[12];
    float* out = (float*)d_out;

    // graph setup (5 kernels)
    k_setup0<<<SCAN_B, 256>>>((const unsigned int*)ei);
    k_count<<<(EE + 255) / 256, 256>>>(ei);
    k_scan1f<<<SCAN_B, 256>>>();
    k_scan23f<<<SCAN_B, 256>>>();
    k_fill<<<(ENT + 255) / 256, 256>>>(ei);

    dim3 ggrid(2, (NN + 127) / 128);

    // layer 1 (A = x fp32, converted in-kernel)
    k_gemm_mma<DIN, true><<<ggrid, 256>>>(x, W1);
    k_agg<1><<<NN, 64>>>(b1);
    // layer 2
    k_gemm_mma<HH, false><<<ggrid, 256>>>(nullptr, W2);
    k_agg<1><<<NN, 64>>>(b2);
    // layer 3
    k_gemm_mma<HH, false><<<ggrid, 256>>>(nullptr, W3);
    k_agg<0><<<NN, 64>>>(b3);

    // pooling + head
    k_pool<<<(NN + 63) / 64, 128>>>(batch);
    k_mlp<<<1, 1024>>>(Wf, bf, Wp, bp, out);
}

// round 17
// speedup vs baseline: 1.1486x; 1.0348x over previous
#include <cuda_runtime.h>
#include <cuda_bf16.h>
#include <cuda_fp16.h>
#include <cuda_fp8.h>
#include <math.h>

// Problem constants (from reference_code)
#define NN   50000
#define EE   1600000
#define ENT  (EE + NN)     // edges incl. self-loops = 1650000
#define DIN  512
#define HH   256
#define GG   16
#define SCAN_B ((NN + 255) / 256)   // 196 scan blocks

// ---------------- device scratch (static; no allocation allowed) ----------------
__device__ int   g_is64;                    // 1 if indices are int64, 0 if int32
__device__ int   g_cnt[NN];
__device__ float g_dinv[NN];
__device__ int   g_rowptr[NN + 1];
__device__ int   g_cursor[NN];
__device__ int   g_bsum[SCAN_B];            // per-block partial sums
__device__ int   g_col[ENT];
__device__ float g_w[ENT];
__device__ float g_pooled[GG * HH];
__device__ int   g_gcount[GG];
// buffers
__device__ __align__(256) unsigned char g_M8[(size_t)NN * HH];   // GEMM out, e4m3 (gather in)
__device__ __nv_bfloat16 g_H16[(size_t)NN * HH];                 // agg out (next layer A)

// dtype-agnostic index load (flag-steered), clamped for crash-safety
__device__ __forceinline__ int load_idx(const void* p, long long i) {
    int v;
    if (g_is64) v = (int)((const long long*)p)[i];
    else        v = ((const int*)p)[i];
    return min(max(v, 0), NN - 1);
}
__device__ __forceinline__ int load_gidx(const void* p, long long i) {
    int v;
    if (g_is64) v = (int)((const long long*)p)[i];
    else        v = ((const int*)p)[i];
    return min(max(v, 0), GG - 1);
}

__device__ __forceinline__ float4 unpack_fp8x4(unsigned v) {
    __half2_raw ha = __nv_cvt_fp8x2_to_halfraw2((__nv_fp8x2_storage_t)(v & 0xFFFF), __NV_E4M3);
    __half2_raw hb = __nv_cvt_fp8x2_to_halfraw2((__nv_fp8x2_storage_t)(v >> 16), __NV_E4M3);
    float2 fa = __half22float2(ha), fb = __half22float2(hb);
    return make_float4(fa.x, fa.y, fb.x, fb.y);
}
__device__ __forceinline__ uint2 pack_bf16x4(float4 v) {
    __nv_bfloat162 lo = __floats2bfloat162_rn(v.x, v.y);
    __nv_bfloat162 hi = __floats2bfloat162_rn(v.z, v.w);
    uint2 r;
    r.x = *(unsigned*)&lo;
    r.y = *(unsigned*)&hi;
    return r;
}

// ---------------- fused setup0: probe dtype + init cnt + zero pool ----------------
__global__ void k_setup0(const unsigned int* __restrict__ w) {
    int gi = blockIdx.x * 256 + threadIdx.x;
    if (gi < NN) g_cnt[gi] = 1;                 // self-loop
    if (gi < GG * HH) g_pooled[gi] = 0.f;
    if (gi < GG) g_gcount[gi] = 0;
    if (blockIdx.x == 0) {                      // dtype probe (block 0 only)
        __shared__ int any;
        if (threadIdx.x == 0) any = 0;
        __syncthreads();
        for (int i = threadIdx.x; i < 2048; i += 256)
            if (w[2 * i + 1] != 0u) atomicOr(&any, 1);
        __syncthreads();
        if (threadIdx.x == 0) g_is64 = (any == 0) ? 1 : 0;
    }
}

__global__ void k_count(const void* __restrict__ ei) {
    int i = blockIdx.x * blockDim.x + threadIdx.x;
    if (i < EE) atomicAdd(&g_cnt[load_idx(ei, (long long)EE + i)], 1);
}

// fused: dinv + cursor init + per-block reduce of cnt -> bsum
__global__ void k_scan1f() {
    __shared__ int sh[256];
    int t = threadIdx.x;
    int i = blockIdx.x * 256 + t;
    int v = 0;
    if (i < NN) {
        v = g_cnt[i];
        g_dinv[i]   = rsqrtf((float)v);
        g_cursor[i] = 0;
    }
    sh[t] = v;
    __syncthreads();
    #pragma unroll
    for (int off = 128; off > 0; off >>= 1) {
        if (t < off) sh[t] += sh[t + off];
        __syncthreads();
    }
    if (t == 0) g_bsum[blockIdx.x] = sh[0];
}

// fused scan2+scan3: every block re-scans the 196 partials, then local scan
__global__ void k_scan23f() {
    __shared__ int sb[256];
    __shared__ int sh[256];
    int t = threadIdx.x;
    int vb = (t < SCAN_B) ? g_bsum[t] : 0;
    sb[t] = vb;
    __syncthreads();
    #pragma unroll
    for (int off = 1; off < 256; off <<= 1) {
        int tv = (t >= off) ? sb[t - off] : 0;
        __syncthreads();
        sb[t] += tv;
        __syncthreads();
    }
    int blk_off = sb[blockIdx.x] - g_bsum[blockIdx.x];   // exclusive offset of this block
    if (blockIdx.x == 0 && t == 255) g_rowptr[NN] = sb[255];
    // local scan
    int i = blockIdx.x * 256 + t;
    int v = (i < NN) ? g_cnt[i] : 0;
    sh[t] = v;
    __syncthreads();
    #pragma unroll
    for (int off = 1; off < 256; off <<= 1) {
        int tv = (t >= off) ? sh[t - off] : 0;
        __syncthreads();
        sh[t] += tv;
        __syncthreads();
    }
    if (i < NN) g_rowptr[i] = blk_off + sh[t] - v;
}

__global__ void k_fill(const void* __restrict__ ei) {
    int i = blockIdx.x * blockDim.x + threadIdx.x;
    if (i >= ENT) return;
    int s, d;
    if (i < EE) { s = load_idx(ei, i); d = load_idx(ei, (long long)EE + i); }
    else        { s = d = i - EE; }
    int pos = atomicAdd(&g_cursor[d], 1);
    int idx = g_rowptr[d] + pos;
    g_col[idx] = s;
    g_w[idx]   = g_dinv[s] * g_dinv[d];
}

// ---------------- pipelined tensor-core GEMM (bf16 MMA, reg-prefetch + dbl smem) ----------------
// g_M8[N,256] = e4m3( A[N,K] @ W[K,256] ); A: fp32 x (FIRST) or bf16 H16; W: fp32 direct.
__device__ __forceinline__ void ldsm_x4(unsigned* r, const void* p) {
    unsigned a = (unsigned)__cvta_generic_to_shared(p);
    asm volatile("ldmatrix.sync.aligned.m8n8.x4.shared.b16 {%0,%1,%2,%3}, [%4];"
                 : "=r"(r[0]), "=r"(r[1]), "=r"(r[2]), "=r"(r[3]) : "r"(a));
}
__device__ __forceinline__ void ldsm_x4t(unsigned* r, const void* p) {
    unsigned a = (unsigned)__cvta_generic_to_shared(p);
    asm volatile("ldmatrix.sync.aligned.m8n8.x4.trans.shared.b16 {%0,%1,%2,%3}, [%4];"
                 : "=r"(r[0]), "=r"(r[1]), "=r"(r[2]), "=r"(r[3]) : "r"(a));
}
__device__ __forceinline__ void mma_bf16(float* c, const unsigned* a, const unsigned* b) {
    asm volatile("mma.sync.aligned.m16n8k16.row.col.f32.bf16.bf16.f32 "
                 "{%0,%1,%2,%3}, {%4,%5,%6,%7}, {%8,%9}, {%0,%1,%2,%3};"
                 : "+f"(c[0]), "+f"(c[1]), "+f"(c[2]), "+f"(c[3])
                 : "r"(a[0]), "r"(a[1]), "r"(a[2]), "r"(a[3]), "r"(b[0]), "r"(b[1]));
}

#define ASTRIDE 40    // 32 + 8 pad (bf16)
#define BSTRIDE 136   // 128 + 8 pad (bf16)

// FIRST=true -> A = x fp32 (K=512, convert on load); else A = g_H16 bf16 (K=256)
template<int K, bool FIRST>
__global__ __launch_bounds__(256) void k_gemm_mma(const float* __restrict__ Ax,
                                                  const float* __restrict__ W) {
    __shared__ __nv_bfloat16 As[2][128 * ASTRIDE];
    __shared__ __nv_bfloat16 Bs[2][32 * BSTRIDE];

    int t      = threadIdx.x;
    int lane   = t & 31;
    int wid    = t >> 5;
    int warp_m = wid >> 2;       // 0..1 -> 64-row band
    int warp_n = wid & 3;        // 0..3 -> 32-col band
    int col0   = blockIdx.x * 128;
    int row0   = blockIdx.y * 128;

    const int NCH = K / 32;

    float acc[4][4][4];
    #pragma unroll
    for (int mt = 0; mt < 4; mt++)
        #pragma unroll
        for (int nt = 0; nt < 4; nt++)
            #pragma unroll
            for (int r = 0; r < 4; r++) acc[mt][nt][r] = 0.f;

    // prefetch registers (converted to bf16 at load)
    uint2 pa[4];     // FIRST path: 4 x 8B chunks of A
    uint4 pa4[2];    // non-FIRST path: 2 x 16B chunks of A
    uint2 pb[4];     // 4 x 8B chunks of B

    // ---- prefetch chunk k0 into registers ----
    auto load_chunk = [&](int k0) {
        if (FIRST) {
            #pragma unroll
            for (int u = 0; u < 4; u++) {
                int idx = t + u * 256;       // 0..1023
                int m   = idx >> 3;          // 0..127
                int q   = idx & 7;           // float4 within 32-k row
                int gr  = row0 + m;
                float4 v = make_float4(0.f, 0.f, 0.f, 0.f);
                if (gr < NN)
                    v = *(const float4*)(Ax + (size_t)gr * K + k0 + q * 4);
                pa[u] = pack_bf16x4(v);
            }
        } else {
            #pragma unroll
            for (int u = 0; u < 2; u++) {
                int idx = t + u * 256;
                int m   = idx >> 2;
                int q   = idx & 3;
                int gr  = row0 + m;
                uint4 v = make_uint4(0u, 0u, 0u, 0u);
                if (gr < NN)
                    v = *(const uint4*)(g_H16 + (size_t)gr * K + k0 + q * 8);
                pa4[u] = v;
            }
        }
        #pragma unroll
        for (int u = 0; u < 4; u++) {
            int idx = t + u * 256;           // 0..1023
            int kk  = idx >> 5;              // 0..31
            int q   = idx & 31;              // float4 within 128-col slice
            float4 v = *(const float4*)(W + (size_t)(k0 + kk) * HH + col0 + q * 4);
            pb[u] = pack_bf16x4(v);
        }
    };

    // ---- store prefetched registers into smem buffer ----
    auto store_chunk = [&](int buf) {
        if (FIRST) {
            #pragma unroll
            for (int u = 0; u < 4; u++) {
                int idx = t + u * 256;
                int m   = idx >> 3;
                int q   = idx & 7;
                *(uint2*)(As[buf] + m * ASTRIDE + q * 4) = pa[u];
            }
        } else {
            #pragma unroll
            for (int u = 0; u < 2; u++) {
                int idx = t + u * 256;
                int m   = idx >> 2;
                int q   = idx & 3;
                *(uint4*)(As[buf] + m * ASTRIDE + q * 8) = pa4[u];
            }
        }
        #pragma unroll
        for (int u = 0; u < 4; u++) {
            int idx = t + u * 256;
            int kk  = idx >> 5;
            int q   = idx & 31;
            *(uint2*)(Bs[buf] + kk * BSTRIDE + q * 4) = pb[u];
        }
    };

    // prologue
    load_chunk(0);
    store_chunk(0);
    __syncthreads();

    int buf = 0;
    for (int ic = 0; ic < NCH; ic++) {
        if (ic + 1 < NCH) load_chunk((ic + 1) * 32);   // global loads overlap compute

        // ---- compute on smem[buf] ----
        #pragma unroll
        for (int ks = 0; ks < 2; ks++) {
            unsigned ah[4][4], bh[4][2];
            int ar = lane & 15;
            int ac = (lane >> 4) * 8;
            #pragma unroll
            for (int mt = 0; mt < 4; mt++)
                ldsm_x4(ah[mt], As[buf] + (warp_m * 64 + mt * 16 + ar) * ASTRIDE + ks * 16 + ac);
            int bg  = lane >> 3;
            int brw = ks * 16 + (bg & 1) * 8 + (lane & 7);
            #pragma unroll
            for (int p = 0; p < 2; p++) {
                int bc = warp_n * 32 + p * 16 + (bg >> 1) * 8;
                unsigned tmp[4];
                ldsm_x4t(tmp, Bs[buf] + brw * BSTRIDE + bc);
                bh[p * 2][0] = tmp[0]; bh[p * 2][1] = tmp[1];
                bh[p * 2 + 1][0] = tmp[2]; bh[p * 2 + 1][1] = tmp[3];
            }
            #pragma unroll
            for (int mt = 0; mt < 4; mt++)
                #pragma unroll
                for (int nt = 0; nt < 4; nt++)
                    mma_bf16(acc[mt][nt], ah[mt], bh[nt]);
        }

        if (ic + 1 < NCH) store_chunk(buf ^ 1);
        __syncthreads();
        buf ^= 1;
    }

    // epilogue: e4m3 store to g_M8
    #pragma unroll
    for (int mt = 0; mt < 4; mt++) {
        int gr0 = row0 + warp_m * 64 + mt * 16 + (lane >> 2);
        #pragma unroll
        for (int nt = 0; nt < 4; nt++) {
            int gc = col0 + warp_n * 32 + nt * 8 + (lane & 3) * 2;
            if (gr0 < NN) {
                __nv_fp8x2_storage_t p01 = __nv_cvt_float2_to_fp8x2(
                    make_float2(acc[mt][nt][0], acc[mt][nt][1]), __NV_SATFINITE, __NV_E4M3);
                *(unsigned short*)(g_M8 + (size_t)gr0 * HH + gc) = p01;
            }
            if (gr0 + 8 < NN) {
                __nv_fp8x2_storage_t p23 = __nv_cvt_float2_to_fp8x2(
                    make_float2(acc[mt][nt][2], acc[mt][nt][3]), __NV_SATFINITE, __NV_E4M3);
                *(unsigned short*)(g_M8 + (size_t)(gr0 + 8) * HH + gc) = p23;
            }
        }
    }
}

// ---------------- CSR gather aggregation (e4m3 in, bf16 out, fp32 accum) ----------------
// one block per dst node; 64 threads, each owns 4 columns (one 4-byte fp8 quad)
template<int DO_RELU>
__global__ __launch_bounds__(64) void k_agg(const float* __restrict__ bias) {
    int n  = blockIdx.x;
    int c4 = threadIdx.x;            // 0..63 -> cols [4c4, 4c4+3]
    int start = g_rowptr[n];
    int end   = g_rowptr[n + 1];
    __shared__ int   scol[64];
    __shared__ float sw[64];
    const unsigned* m = (const unsigned*)g_M8;
    float4 a0 = make_float4(0.f, 0.f, 0.f, 0.f), a1 = a0;
    for (int e0 = start; e0 < end; e0 += 64) {
        int cnt = min(64, end - e0);
        if (c4 < cnt) { scol[c4] = g_col[e0 + c4]; sw[c4] = g_w[e0 + c4]; }
        __syncthreads();
        int j = 0;
        for (; j + 2 <= cnt; j += 2) {
            unsigned v0 = __ldg(m + (size_t)scol[j + 0] * 64 + c4);
            unsigned v1 = __ldg(m + (size_t)scol[j + 1] * 64 + c4);
            float w0 = sw[j + 0], w1 = sw[j + 1];
            float4 f0 = unpack_fp8x4(v0);
            float4 f1 = unpack_fp8x4(v1);
            a0.x = fmaf(f0.x, w0, a0.x); a0.y = fmaf(f0.y, w0, a0.y);
            a0.z = fmaf(f0.z, w0, a0.z); a0.w = fmaf(f0.w, w0, a0.w);
            a1.x = fmaf(f1.x, w1, a1.x); a1.y = fmaf(f1.y, w1, a1.y);
            a1.z = fmaf(f1.z, w1, a1.z); a1.w = fmaf(f1.w, w1, a1.w);
        }
        for (; j < cnt; j++) {
            unsigned v = __ldg(m + (size_t)scol[j] * 64 + c4);
            float w = sw[j];
            float4 f = unpack_fp8x4(v);
            a0.x = fmaf(f.x, w, a0.x); a0.y = fmaf(f.y, w, a0.y);
            a0.z = fmaf(f.z, w, a0.z); a0.w = fmaf(f.w, w, a0.w);
        }
        __syncthreads();
    }
    float r0 = a0.x + a1.x + bias[4 * c4 + 0];
    float r1 = a0.y + a1.y + bias[4 * c4 + 1];
    float r2 = a0.z + a1.z + bias[4 * c4 + 2];
    float r3 = a0.w + a1.w + bias[4 * c4 + 3];
    if (DO_RELU) {
        r0 = fmaxf(r0, 0.f); r1 = fmaxf(r1, 0.f);
        r2 = fmaxf(r2, 0.f); r3 = fmaxf(r3, 0.f);
    }
    __nv_bfloat162* hp = (__nv_bfloat162*)(g_H16 + (size_t)n * HH + 4 * c4);
    hp[0] = __floats2bfloat162_rn(r0, r1);
    hp[1] = __floats2bfloat162_rn(r2, r3);
}

// ---------------- pooling ----------------
// block = 64 nodes x 128 col-pairs; batch sorted -> few boundaries per chunk
__global__ __launch_bounds__(128) void k_pool(const void* __restrict__ batch) {
    int base = blockIdx.x * 64;
    int c2 = threadIdx.x;
    __shared__ int sg[64];
    int nmax = min(64, NN - base);
    if (nmax <= 0) return;
    if (c2 < nmax) sg[c2] = load_gidx(batch, base + c2);
    __syncthreads();
    const __nv_bfloat162* h = (const __nv_bfloat162*)g_H16;
    int gprev = sg[0];
    float2 acc = make_float2(0.f, 0.f);
    for (int i = 0; i < nmax; i++) {
        int g = sg[i];
        if (g != gprev) {
            atomicAdd(&g_pooled[gprev * HH + 2 * c2], acc.x);
            atomicAdd(&g_pooled[gprev * HH + 2 * c2 + 1], acc.y);
            acc = make_float2(0.f, 0.f);
            gprev = g;
        }
        float2 v = __bfloat1622float2(h[(size_t)(base + i) * 128 + c2]);
        acc.x += v.x; acc.y += v.y;
    }
    atomicAdd(&g_pooled[gprev * HH + 2 * c2], acc.x);
    atomicAdd(&g_pooled[gprev * HH + 2 * c2 + 1], acc.y);
    if (c2 < nmax) atomicAdd(&g_gcount[sg[c2]], 1);
}

// ---------------- final MLP + sigmoid ----------------
__global__ __launch_bounds__(1024) void k_mlp(const float* __restrict__ Wf,
                                              const float* __restrict__ bf,
                                              const float* __restrict__ Wp,
                                              const float* __restrict__ bp,
                                              float* __restrict__ out) {
    __shared__ float pm[GG * HH];
    __shared__ float fsh[GG * 64];
    int t = threadIdx.x;
    for (int i = t; i < GG * HH; i += 1024) {
        int g = i / HH;
        float cnt = fmaxf((float)g_gcount[g], 1.f);
        pm[i] = g_pooled[i] / cnt;
    }
    __syncthreads();
    int g  = t >> 6;
    int oc = t & 63;
    float f = bf[oc];
    #pragma unroll 8
    for (int k = 0; k < HH; k++)
        f = fmaf(pm[g * HH + k], Wf[k * 64 + oc], f);
    fsh[g * 64 + oc] = f;
    __syncthreads();
    if (t < GG) {
        float o = bp[0];
        #pragma unroll
        for (int j = 0; j < 64; j++)
            o = fmaf(fsh[t * 64 + j], Wp[j], o);
        out[t] = 1.f / (1.f + expf(-o));
    }
}

// ---------------- launch ----------------
extern "C" void kernel_launch(void* const* d_in, const int* in_sizes, int n_in,
                              void* d_out, int out_size) {
    const float* x     = (const float*)d_in[0];
    const void*  ei    = d_in[1];   // [2, E] int32 or int64 (probed on device)
    const void*  batch = d_in[2];
    const float* W1 = (const float*)d_in[3];
    const float* b1 = (const float*)d_in[4];
    const float* W2 = (const float*)d_in[5];
    const float* b2 = (const float*)d_in[6];
    const float* W3 = (const float*)d_in[7];
    const float* b3 = (const float*)d_in[8];
    const float* Wf = (const float*)d_in[9];
    const float* bf = (const float*)d_in[10];
    const float* Wp = (const float*)d_in[11];
    const float* bp = (const float*)d_in[12];
    float* out = (float*)d_out;

    // one-time host-side stream/event infra (no device memory involved)
    static cudaStream_t s2 = nullptr;
    static cudaEvent_t evFork = nullptr, evJoin = nullptr;
    if (s2 == nullptr) {
        cudaStreamCreateWithFlags(&s2, cudaStreamNonBlocking);
        cudaEventCreateWithFlags(&evFork, cudaEventDisableTiming);
        cudaEventCreateWithFlags(&evJoin, cudaEventDisableTiming);
    }

    // ---- fork: graph setup on s2, layer-1 GEMM (independent) on main stream ----
    cudaEventRecord(evFork, 0);
    cudaStreamWaitEvent(s2, evFork, 0);

    k_setup0<<<SCAN_B, 256, 0, s2>>>((const unsigned int*)ei);
    k_count<<<(EE + 255) / 256, 256, 0, s2>>>(ei);
    k_scan1f<<<SCAN_B, 256, 0, s2>>>();
    k_scan23f<<<SCAN_B, 256, 0, s2>>>();
    k_fill<<<(ENT + 255) / 256, 256, 0, s2>>>(ei);
    cudaEventRecord(evJoin, s2);

    dim3 ggrid(2, (NN + 127) / 128);

    // layer 1 GEMM (A = x fp32, converted in-kernel) — concurrent with setup
    k_gemm_mma<DIN, true><<<ggrid, 256>>>(x, W1);

    // ---- join: aggregation needs the CSR ----
    cudaStreamWaitEvent(0, evJoin, 0);
    k_agg<1><<<NN, 64>>>(b1);
    // layer 2
    k_gemm_mma<HH, false><<<ggrid, 256>>>(nullptr, W2);
    k_agg<1><<<NN, 64>>>(b2);
    // layer 3
    k_gemm_mma<HH, false><<<ggrid, 256>>>(nullptr, W3);
    k_agg<0><<<NN, 64>>>(b3);

    // pooling + head
    k_pool<<<(NN + 63) / 64, 128>>>(batch);
    k_mlp<<<1, 1024>>>(Wf, bf, Wp, bp, out);
}